// round 3
// baseline (speedup 1.0000x reference)
#include <cuda_runtime.h>
#include <cuda_bf16.h>
#include <cstdint>

#define BB 4
#define CC 19
#define HH 512
#define WW 1024
#define HW (HH * WW)            // 524288 = 2^19
#define NPIX (BB * HW)          // 2097152
#define NBC (BB * CC)           // 76
#define NBLK_MAIN 2048          // (NPIX/4) / 256

#define BINS1 576               // 16-bit prefix bins: (u>>16) - BASE1
#define BASE1 0x3D50u           // min u>>16 is 0x3D57 (1/19); margin below
#define ECAP 8192               // candidate cap per (b,c); expected ~300

// ---------------- device scratch (static, zero-init at load) ----------------
__device__ unsigned int  g_u[NPIX];            // float bits of max_prob = 1/s
__device__ unsigned char g_cls[NPIX];          // argmax class
__device__ unsigned int  g_hist1[NBC * BINS1];
__device__ unsigned int  g_prefix[NBC];        // selected u>>16; 0xFFFFFFFF = inactive
__device__ unsigned int  g_r[NBC];             // 1-indexed rank within prefix bin
__device__ unsigned int  g_tbits[NBC];         // exact k-th largest u; 0xFFFFFFFF = none
__device__ unsigned int  g_eqn[NBC];           // candidate counts (reset by selfine)
__device__ unsigned int  g_cand[NBC * ECAP];   // candidate u values
__device__ float         g_eqsum[NBC];         // m * nll(tbits) (0 if prob>0.9)
__device__ float         g_blocksum[NBLK_MAIN];
__device__ unsigned int  g_done;               // last-block counter (reset each use)

// ---------------- 2-barrier suffix scan (bin t ascending; suf = sum[t..N)) --
__device__ __forceinline__ unsigned suffix_scan(unsigned v, int t, int nwarps,
                                                unsigned* wsum) {
    unsigned lane = t & 31, w = (unsigned)t >> 5;
    unsigned x = v;
#pragma unroll
    for (int d = 1; d < 32; d <<= 1) {
        unsigned y = __shfl_down_sync(0xFFFFFFFFu, x, d);
        if (lane + d < 32) x += y;
    }
    if (lane == 0) wsum[w] = x;                 // warp total
    __syncthreads();
    if (w == 0) {
        unsigned wv = (lane < (unsigned)nwarps) ? wsum[lane] : 0u;
        unsigned own = wv;
#pragma unroll
        for (int d = 1; d < 32; d <<= 1) {
            unsigned y = __shfl_down_sync(0xFFFFFFFFu, wv, d);
            if (lane + d < 32) wv += y;
        }
        if (lane < (unsigned)nwarps) wsum[lane] = wv - own;   // exclusive suffix
    }
    __syncthreads();
    return x + wsum[w];                         // inclusive suffix over all bins
}

// ---------------- main: online softmax + 16-bit-prefix shared histogram -----
#define UPD(V, MX, S, AM, C)                                                   \
    if ((V) > (MX)) { (S) = (S) * __expf((MX) - (V)) + 1.0f; (MX) = (V); (AM) = (C); } \
    else            { (S) += __expf((V) - (MX)); }

__global__ void __launch_bounds__(256) k_compute(const float* __restrict__ pred) {
    __shared__ unsigned int shist[CC * BINS1];  // 10944 u32 = 43.8 KB
    unsigned int tx = threadIdx.x;
    unsigned int t  = blockIdx.x * 256 + tx;
    unsigned int p0 = t << 2;
    unsigned int b  = blockIdx.x >> 9;          // 512 blocks per image
    unsigned int n  = p0 & (HW - 1);

    for (int i = tx; i < CC * BINS1; i += 256) shist[i] = 0;
    __syncthreads();

    const float4* base = reinterpret_cast<const float4*>(pred + (size_t)b * CC * HW + n);
    const unsigned int cs = HW / 4;

    float4 x = __ldg(base);
    float m0 = x.x, m1 = x.y, m2 = x.z, m3 = x.w;
    float s0 = 1.f, s1 = 1.f, s2 = 1.f, s3 = 1.f;
    int   a0 = 0, a1 = 0, a2 = 0, a3 = 0;

#pragma unroll
    for (int c = 1; c < CC; c++) {
        float4 v = __ldg(base + (size_t)c * cs);
        UPD(v.x, m0, s0, a0, c);
        UPD(v.y, m1, s1, a1, c);
        UPD(v.z, m2, s2, a2, c);
        UPD(v.w, m3, s3, a3, c);
    }

    unsigned int u0 = __float_as_uint(1.0f / s0), u1 = __float_as_uint(1.0f / s1);
    unsigned int u2 = __float_as_uint(1.0f / s2), u3 = __float_as_uint(1.0f / s3);

    *reinterpret_cast<uint4*>(g_u + p0) = make_uint4(u0, u1, u2, u3);
    *reinterpret_cast<uchar4*>(g_cls + p0) =
        make_uchar4((unsigned char)a0, (unsigned char)a1, (unsigned char)a2, (unsigned char)a3);

#define H1(U, A) {                                                             \
        int bin = (int)((U) >> 16) - (int)BASE1;                               \
        bin = bin < 0 ? 0 : (bin > BINS1 - 1 ? BINS1 - 1 : bin);               \
        atomicAdd(&shist[(unsigned)(A) * BINS1 + (unsigned)bin], 1u); }
    H1(u0, a0); H1(u1, a1); H1(u2, a2); H1(u3, a3);
#undef H1
    __syncthreads();

    for (int i = tx; i < CC * BINS1; i += 256) {
        unsigned int v = shist[i];
        if (v) atomicAdd(&g_hist1[b * (CC * BINS1) + i], v);
    }
}

// ---------------- select 16-bit prefix + rank (576 threads, warp scan) ------
__global__ void __launch_bounds__(576) k_sel1() {
    __shared__ unsigned wsum[32];
    __shared__ unsigned tot;
    int bc = blockIdx.x;
    int t  = threadIdx.x;

    unsigned v = g_hist1[bc * BINS1 + t];
    unsigned suf = suffix_scan(v, t, 18, wsum);
    if (t == 0) tot = suf;
    __syncthreads();

    unsigned k = (unsigned)floorf((float)tot * 0.66f);
    if (k == 0) {
        if (t == 0) { g_prefix[bc] = 0xFFFFFFFFu; g_r[bc] = 0; }
    } else if (v && suf >= k && suf - v < k) {
        g_prefix[bc] = (unsigned)t + BASE1;
        g_r[bc]      = k - (suf - v);
    }
    g_hist1[bc * BINS1 + t] = 0;                // clean for next replay
}

// ---------------- compact: gather pixels matching the 16-bit prefix ---------
__global__ void __launch_bounds__(256) k_compact() {
    __shared__ unsigned spfx[CC];
    unsigned int tx = threadIdx.x;
    unsigned int t  = blockIdx.x * 256 + tx;
    unsigned int p0 = t << 2;
    unsigned int b  = blockIdx.x >> 9;
    if (tx < CC) spfx[tx] = g_prefix[b * CC + tx];
    __syncthreads();

    uint4  u  = *reinterpret_cast<const uint4*>(g_u + p0);
    uchar4 cl = *reinterpret_cast<const uchar4*>(g_cls + p0);
#define CP(U, C) {                                                             \
        if (((U) >> 16) == spfx[(C)]) {                                        \
            unsigned bc = b * CC + (unsigned)(C);                              \
            unsigned pos = atomicAdd(&g_eqn[bc], 1u);                          \
            if (pos < ECAP) g_cand[bc * ECAP + pos] = (U); } }
    CP(u.x, cl.x); CP(u.y, cl.y); CP(u.z, cl.z); CP(u.w, cl.w);
#undef CP
}

// ---------------- exact threshold among candidates (two 8-bit levels) -------
__global__ void __launch_bounds__(256) k_selfine() {
    __shared__ unsigned hist[256];
    __shared__ unsigned wsum[32];
    __shared__ unsigned sb1, sr2;
    int bc = blockIdx.x;
    int t  = threadIdx.x;

    unsigned prefix = g_prefix[bc];
    if (prefix == 0xFFFFFFFFu) {
        if (t == 0) { g_tbits[bc] = 0xFFFFFFFFu; g_eqsum[bc] = 0.f; g_eqn[bc] = 0; }
        return;
    }
    unsigned E = g_eqn[bc]; if (E > ECAP) E = ECAP;
    unsigned r = g_r[bc];
    const unsigned* cand = g_cand + bc * ECAP;

    // level 1: bits 15..8
    hist[t] = 0; __syncthreads();
    for (unsigned i = t; i < E; i += 256) atomicAdd(&hist[(cand[i] >> 8) & 255u], 1u);
    __syncthreads();
    unsigned v = hist[t];
    unsigned suf = suffix_scan(v, t, 8, wsum);
    if (v && suf >= r && suf - v < r) { sb1 = (unsigned)t; sr2 = r - (suf - v); }
    __syncthreads();
    unsigned b1 = sb1, r2 = sr2;

    // level 2: bits 7..0
    hist[t] = 0; __syncthreads();
    for (unsigned i = t; i < E; i += 256) {
        unsigned u = cand[i];
        if (((u >> 8) & 255u) == b1) atomicAdd(&hist[u & 255u], 1u);
    }
    __syncthreads();
    v = hist[t];
    suf = suffix_scan(v, t, 8, wsum);
    if (v && suf >= r2 && suf - v < r2) {
        unsigned tb = (prefix << 16) | (b1 << 8) | (unsigned)t;
        unsigned m  = r2 - (suf - v);               // # ties kept in top-k
        g_tbits[bc] = tb;
        float p = __uint_as_float(tb);
        // ties all share nll = -log(p); prob>0.9 ties counted in k_final instead
        g_eqsum[bc] = (p > 0.9f) ? 0.f : (float)m * (-__logf(p));
    }
    if (t == 0) g_eqn[bc] = 0;                      // reset for next replay
}

// ---------------- final mask + sum; fused scalar output (last-block) --------
__global__ void __launch_bounds__(256) k_final(float* __restrict__ out) {
    __shared__ unsigned stb[CC];
    __shared__ float red[256];
    __shared__ bool last;
    unsigned int tx = threadIdx.x;
    unsigned int t  = blockIdx.x * 256 + tx;
    unsigned int p0 = t << 2;
    unsigned int b  = blockIdx.x >> 9;
    if (tx < CC) stb[tx] = g_tbits[b * CC + tx];
    __syncthreads();

    uint4  u  = *reinterpret_cast<const uint4*>(g_u + p0);
    uchar4 cl = *reinterpret_cast<const uchar4*>(g_cls + p0);

    float local = 0.f;
#define LANE(U, C) {                                                           \
        unsigned tb = stb[(C)];                                                \
        float p = __uint_as_float(U);                                          \
        if (p > 0.9f || (U) > tb) local += -__logf(p); }
    LANE(u.x, cl.x); LANE(u.y, cl.y); LANE(u.z, cl.z); LANE(u.w, cl.w);
#undef LANE

    red[tx] = local;
    __syncthreads();
    for (int s = 128; s > 0; s >>= 1) {
        if (tx < s) red[tx] += red[tx + s];
        __syncthreads();
    }
    if (tx == 0) {
        g_blocksum[blockIdx.x] = red[0];
        __threadfence();
        last = (atomicAdd(&g_done, 1u) == NBLK_MAIN - 1);
    }
    __syncthreads();

    if (last) {                                      // deterministic final reduce
        __shared__ double dred[256];
        double acc = 0.0;
        for (int i = tx; i < NBLK_MAIN; i += 256) acc += (double)g_blocksum[i];
        if (tx < NBC) acc += (double)g_eqsum[tx];
        dred[tx] = acc;
        __syncthreads();
        for (int s = 128; s > 0; s >>= 1) {
            if (tx < s) dred[tx] += dred[tx + s];
            __syncthreads();
        }
        if (tx == 0) {
            out[0] = (float)(dred[0] * (1.0 / (double)NPIX));
            g_done = 0;                              // reset for next replay
        }
    }
}

// ---------------- launcher ---------------------------------------------------
extern "C" void kernel_launch(void* const* d_in, const int* in_sizes, int n_in,
                              void* d_out, int out_size) {
    const float* pred = (const float*)d_in[0];
    float* out = (float*)d_out;
    (void)in_sizes; (void)n_in; (void)out_size;

    k_compute<<<NBLK_MAIN, 256>>>(pred);
    k_sel1<<<NBC, BINS1>>>();
    k_compact<<<NBLK_MAIN, 256>>>();
    k_selfine<<<NBC, 256>>>();
    k_final<<<NBLK_MAIN, 256>>>(out);
}

// round 4
// speedup vs baseline: 1.0972x; 1.0972x over previous
#include <cuda_runtime.h>
#include <cuda_bf16.h>
#include <cstdint>

#define BB 4
#define CC 19
#define HH 512
#define WW 1024
#define HW (HH * WW)            // 524288 = 2^19
#define NPIX (BB * HW)          // 2097152
#define NBC (BB * CC)           // 76
#define NBLK_MAIN 2048          // (NPIX/4) / 256

#define BINS1 160               // 14-bit prefix bins: (u>>18) - BASE1
#define BASE1 0xF50u            // u>>18 in [0xF55, 0xFE0] for p in (1/19, 1]
#define ECAP  16384             // candidate cap per (b,c); expected ~1-2k

// ---------------- device scratch (static, zero-init at load) ----------------
__device__ unsigned int  g_u[NPIX];            // float bits of max_prob = 1/s
__device__ unsigned char g_cls[NPIX];          // argmax class
__device__ unsigned int  g_hist1[NBC * BINS1];
__device__ unsigned int  g_binT[NBC];          // threshold bin (u>>18); 0xFFFFFFFF = no topk
__device__ unsigned int  g_r[NBC];             // 1-indexed rank within threshold bin
__device__ unsigned int  g_eqn[NBC];           // candidate counts (reset by selfine)
__device__ unsigned int  g_cand[NBC * ECAP];   // candidate u values
__device__ float         g_eqsum[NBC];         // per-(b,c) candidate+tie contribution
__device__ float         g_blocksum[NBLK_MAIN];
__device__ unsigned int  g_done;               // last-block counter (reset each use)

// ---------------- 2-barrier suffix scan (bin t ascending; suf = sum[t..N)) --
__device__ __forceinline__ unsigned suffix_scan(unsigned v, int t, int nwarps,
                                                unsigned* wsum) {
    unsigned lane = t & 31, w = (unsigned)t >> 5;
    unsigned x = v;
#pragma unroll
    for (int d = 1; d < 32; d <<= 1) {
        unsigned y = __shfl_down_sync(0xFFFFFFFFu, x, d);
        if (lane + d < 32) x += y;
    }
    if (lane == 0) wsum[w] = x;                 // warp total
    __syncthreads();
    if (w == 0) {
        unsigned wv = (lane < (unsigned)nwarps) ? wsum[lane] : 0u;
        unsigned own = wv;
#pragma unroll
        for (int d = 1; d < 32; d <<= 1) {
            unsigned y = __shfl_down_sync(0xFFFFFFFFu, wv, d);
            if (lane + d < 32) wv += y;
        }
        if (lane < (unsigned)nwarps) wsum[lane] = wv - own;   // exclusive suffix
    }
    __syncthreads();
    return x + wsum[w];                         // inclusive suffix over all bins
}

// ---------------- main: online softmax + 160-bin shared histogram -----------
#define UPD(V, MX, S, AM, C)                                                   \
    if ((V) > (MX)) { (S) = (S) * __expf((MX) - (V)) + 1.0f; (MX) = (V); (AM) = (C); } \
    else            { (S) += __expf((V) - (MX)); }

__global__ void __launch_bounds__(256) k_compute(const float* __restrict__ pred) {
    __shared__ unsigned int shist[CC * BINS1];  // 3040 u32 = 12.16 KB
    unsigned int tx = threadIdx.x;
    unsigned int t  = blockIdx.x * 256 + tx;
    unsigned int p0 = t << 2;
    unsigned int b  = blockIdx.x >> 9;          // 512 blocks per image
    unsigned int n  = p0 & (HW - 1);

#pragma unroll
    for (int i = tx; i < CC * BINS1; i += 256) shist[i] = 0;
    __syncthreads();

    const float4* base = reinterpret_cast<const float4*>(pred + (size_t)b * CC * HW + n);
    const unsigned int cs = HW / 4;

    float4 x = __ldg(base);
    float m0 = x.x, m1 = x.y, m2 = x.z, m3 = x.w;
    float s0 = 1.f, s1 = 1.f, s2 = 1.f, s3 = 1.f;
    int   a0 = 0, a1 = 0, a2 = 0, a3 = 0;

#pragma unroll
    for (int c = 1; c < CC; c++) {
        float4 v = __ldg(base + (size_t)c * cs);
        UPD(v.x, m0, s0, a0, c);
        UPD(v.y, m1, s1, a1, c);
        UPD(v.z, m2, s2, a2, c);
        UPD(v.w, m3, s3, a3, c);
    }

    unsigned int u0 = __float_as_uint(1.0f / s0), u1 = __float_as_uint(1.0f / s1);
    unsigned int u2 = __float_as_uint(1.0f / s2), u3 = __float_as_uint(1.0f / s3);

    *reinterpret_cast<uint4*>(g_u + p0) = make_uint4(u0, u1, u2, u3);
    *reinterpret_cast<uchar4*>(g_cls + p0) =
        make_uchar4((unsigned char)a0, (unsigned char)a1, (unsigned char)a2, (unsigned char)a3);

#define H1(U, A) {                                                             \
        int bin = (int)((U) >> 18) - (int)BASE1;                               \
        bin = bin < 0 ? 0 : (bin > BINS1 - 1 ? BINS1 - 1 : bin);               \
        atomicAdd(&shist[(unsigned)(A) * BINS1 + (unsigned)bin], 1u); }
    H1(u0, a0); H1(u1, a1); H1(u2, a2); H1(u3, a3);
#undef H1
    __syncthreads();

#pragma unroll
    for (int i = tx; i < CC * BINS1; i += 256) {
        unsigned int v = shist[i];
        if (v) atomicAdd(&g_hist1[b * (CC * BINS1) + i], v);
    }
}

// ---------------- select threshold bin + rank (160 threads, warp scan) ------
__global__ void __launch_bounds__(160) k_sel1() {
    __shared__ unsigned wsum[32];
    __shared__ unsigned tot;
    int bc = blockIdx.x;
    int t  = threadIdx.x;

    unsigned v = g_hist1[bc * BINS1 + t];
    unsigned suf = suffix_scan(v, t, 5, wsum);
    if (t == 0) tot = suf;
    __syncthreads();

    unsigned k = (unsigned)floorf((float)tot * 0.66f);
    if (k == 0) {
        if (t == 0) { g_binT[bc] = 0xFFFFFFFFu; g_r[bc] = 0; }
    } else if (v && suf >= k && suf - v < k) {
        g_binT[bc] = (unsigned)t + BASE1;       // == (u >> 18) of threshold
        g_r[bc]    = k - (suf - v);             // 1-indexed rank within bin
    }
    g_hist1[bc * BINS1 + t] = 0;                // clean for next replay
}

// ---------------- compact + definite-pixel sum (fused old k_final) ----------
__global__ void __launch_bounds__(256) k_compact() {
    __shared__ unsigned sbinT[CC];
    __shared__ float red[256];
    unsigned int tx = threadIdx.x;
    unsigned int t  = blockIdx.x * 256 + tx;
    unsigned int p0 = t << 2;
    unsigned int b  = blockIdx.x >> 9;
    if (tx < CC) sbinT[tx] = g_binT[b * CC + tx];
    __syncthreads();

    uint4  u  = *reinterpret_cast<const uint4*>(g_u + p0);
    uchar4 cl = *reinterpret_cast<const uchar4*>(g_cls + p0);

    float local = 0.f;
#define LANE(U, C) {                                                           \
        unsigned bt = sbinT[(C)];                                              \
        unsigned bin = (U) >> 18;                                              \
        float p = __uint_as_float(U);                                          \
        if (bin > bt) local += -__logf(p);                                     \
        else if (bin == bt) {                                                  \
            unsigned bc = b * CC + (unsigned)(C);                              \
            unsigned pos = atomicAdd(&g_eqn[bc], 1u);                          \
            if (pos < ECAP) g_cand[bc * ECAP + pos] = (U);                     \
        } else if (p > 0.9f) local += -__logf(p); }
    LANE(u.x, cl.x); LANE(u.y, cl.y); LANE(u.z, cl.z); LANE(u.w, cl.w);
#undef LANE

    red[tx] = local;
    __syncthreads();
#pragma unroll
    for (int s = 128; s > 0; s >>= 1) {
        if (tx < s) red[tx] += red[tx + s];
        __syncthreads();
    }
    if (tx == 0) g_blocksum[blockIdx.x] = red[0];
}

// ---------------- exact threshold among candidates + final scalar -----------
__global__ void __launch_bounds__(512) k_selfine(float* __restrict__ out) {
    __shared__ unsigned hist[512];
    __shared__ unsigned wsum[32];
    __shared__ unsigned sb1, sr2, stb, sm;
    __shared__ float red[512];
    __shared__ bool last;
    int bc = blockIdx.x;
    int t  = threadIdx.x;

    unsigned binT = g_binT[bc];
    float eq = 0.f;

    if (binT != 0xFFFFFFFFu) {
        unsigned E = g_eqn[bc]; if (E > ECAP) E = ECAP;
        unsigned r = g_r[bc];
        const unsigned* cand = g_cand + bc * ECAP;

        // level 1: bits 17..9
        hist[t] = 0; __syncthreads();
        for (unsigned i = t; i < E; i += 512)
            atomicAdd(&hist[(cand[i] >> 9) & 511u], 1u);
        __syncthreads();
        unsigned v = hist[t];
        unsigned suf = suffix_scan(v, t, 16, wsum);
        if (v && suf >= r && suf - v < r) { sb1 = (unsigned)t; sr2 = r - (suf - v); }
        __syncthreads();
        unsigned b1 = sb1, r2 = sr2;

        // level 2: bits 8..0
        hist[t] = 0; __syncthreads();
        for (unsigned i = t; i < E; i += 512) {
            unsigned u = cand[i];
            if (((u >> 9) & 511u) == b1) atomicAdd(&hist[u & 511u], 1u);
        }
        __syncthreads();
        v = hist[t];
        suf = suffix_scan(v, t, 16, wsum);
        if (v && suf >= r2 && suf - v < r2) {
            stb = (binT << 18) | (b1 << 9) | (unsigned)t;   // exact k-th largest u
            sm  = r2 - (suf - v);                           // # ties kept in top-k
        }
        __syncthreads();
        unsigned tb = stb, m = sm;

        // candidate contributions: strictly above tb, or prob-mask
        for (unsigned i = t; i < E; i += 512) {
            unsigned u = cand[i];
            float p = __uint_as_float(u);
            if (u > tb || p > 0.9f) eq += -__logf(p);
        }
        // ties at tb (p <= 0.9): exactly m of them are kept by top-k rank
        float ptb = __uint_as_float(tb);
        if (t == 0 && ptb <= 0.9f) eq += (float)m * (-__logf(ptb));
        if (t == 0) g_eqn[bc] = 0;                          // reset for replay
    } else {
        if (t == 0) g_eqn[bc] = 0;
    }

    red[t] = eq;
    __syncthreads();
#pragma unroll
    for (int s = 256; s > 0; s >>= 1) {
        if (t < s) red[t] += red[t + s];
        __syncthreads();
    }
    if (t == 0) {
        g_eqsum[bc] = red[0];
        __threadfence();
        last = (atomicAdd(&g_done, 1u) == NBC - 1);
    }
    __syncthreads();

    if (last) {                                             // final scalar reduce
        __shared__ double dred[512];
        double acc = 0.0;
        for (int i = t; i < NBLK_MAIN; i += 512) acc += (double)g_blocksum[i];
        if (t < NBC) acc += (double)g_eqsum[t];
        dred[t] = acc;
        __syncthreads();
#pragma unroll
        for (int s = 256; s > 0; s >>= 1) {
            if (t < s) dred[t] += dred[t + s];
            __syncthreads();
        }
        if (t == 0) {
            out[0] = (float)(dred[0] * (1.0 / (double)NPIX));
            g_done = 0;                                     // reset for replay
        }
    }
}

// ---------------- launcher ---------------------------------------------------
extern "C" void kernel_launch(void* const* d_in, const int* in_sizes, int n_in,
                              void* d_out, int out_size) {
    const float* pred = (const float*)d_in[0];
    float* out = (float*)d_out;
    (void)in_sizes; (void)n_in; (void)out_size;

    k_compute<<<NBLK_MAIN, 256>>>(pred);
    k_sel1<<<NBC, BINS1>>>();
    k_compact<<<NBLK_MAIN, 256>>>();
    k_selfine<<<NBC, 512>>>(out);
}

// round 5
// speedup vs baseline: 1.4037x; 1.2794x over previous
#include <cuda_runtime.h>
#include <cuda_bf16.h>
#include <cstdint>

#define BB 4
#define CC 19
#define HH 512
#define WW 1024
#define HW (HH * WW)            // 524288 = 2^19
#define NPIX (BB * HW)          // 2097152
#define NBC (BB * CC)           // 76
#define NBLK_MAIN 2048          // (NPIX/4) / 256

#define BINS1 160               // 14-bit prefix bins: (key>>18) - BASE1
#define BASE1 0xF50u            // u>>18 in [0xF55, 0xFE0] for p in (1/19, 1]
#define NSEG  32                // candidate-counter spread factor
#define SEGCAP 512              // per-segment candidate capacity

// ---------------- device scratch (static, zero-init at load) ----------------
// key = (float_bits(max_prob) & 0xFFFFFF00) | argmax_class
__device__ unsigned int  g_key[NPIX];
__device__ unsigned int  g_hist1[NBC * BINS1];
__device__ unsigned int  g_binT[NBC];          // threshold bin (key>>18); 0xFFFFFFFF = none
__device__ unsigned int  g_r[NBC];             // 1-indexed rank within threshold bin
__device__ unsigned int  g_eqn[NBC * NSEG];    // segmented candidate counts
__device__ unsigned int  g_cand[NBC * NSEG * SEGCAP];
__device__ float         g_eqsum[NBC];
__device__ float         g_blocksum[NBLK_MAIN];
__device__ unsigned int  g_done;

// ---------------- 2-barrier suffix scan (bin t ascending; suf = sum[t..N)) --
__device__ __forceinline__ unsigned suffix_scan(unsigned v, int t, int nwarps,
                                                unsigned* wsum) {
    unsigned lane = t & 31, w = (unsigned)t >> 5;
    unsigned x = v;
#pragma unroll
    for (int d = 1; d < 32; d <<= 1) {
        unsigned y = __shfl_down_sync(0xFFFFFFFFu, x, d);
        if (lane + d < 32) x += y;
    }
    if (lane == 0) wsum[w] = x;
    __syncthreads();
    if (w == 0) {
        unsigned wv = (lane < (unsigned)nwarps) ? wsum[lane] : 0u;
        unsigned own = wv;
#pragma unroll
        for (int d = 1; d < 32; d <<= 1) {
            unsigned y = __shfl_down_sync(0xFFFFFFFFu, wv, d);
            if (lane + d < 32) wv += y;
        }
        if (lane < (unsigned)nwarps) wsum[lane] = wv - own;   // exclusive suffix
    }
    __syncthreads();
    return x + wsum[w];
}

// ---------------- main: online softmax + 160-bin shared histogram -----------
#define UPD(V, MX, S, AM, C)                                                   \
    if ((V) > (MX)) { (S) = (S) * __expf((MX) - (V)) + 1.0f; (MX) = (V); (AM) = (C); } \
    else            { (S) += __expf((V) - (MX)); }

__global__ void __launch_bounds__(256) k_compute(const float* __restrict__ pred) {
    __shared__ unsigned int shist[CC * BINS1];  // 12.16 KB
    unsigned int tx = threadIdx.x;
    unsigned int t  = blockIdx.x * 256 + tx;
    unsigned int p0 = t << 2;
    unsigned int b  = blockIdx.x >> 9;          // 512 blocks per image
    unsigned int n  = p0 & (HW - 1);

#pragma unroll
    for (int i = tx; i < CC * BINS1; i += 256) shist[i] = 0;
    __syncthreads();

    const float4* base = reinterpret_cast<const float4*>(pred + (size_t)b * CC * HW + n);
    const unsigned int cs = HW / 4;

    float4 x = __ldg(base);
    float m0 = x.x, m1 = x.y, m2 = x.z, m3 = x.w;
    float s0 = 1.f, s1 = 1.f, s2 = 1.f, s3 = 1.f;
    int   a0 = 0, a1 = 0, a2 = 0, a3 = 0;

#pragma unroll
    for (int c = 1; c < CC; c++) {
        float4 v = __ldg(base + (size_t)c * cs);
        UPD(v.x, m0, s0, a0, c);
        UPD(v.y, m1, s1, a1, c);
        UPD(v.z, m2, s2, a2, c);
        UPD(v.w, m3, s3, a3, c);
    }

    unsigned int u0 = (__float_as_uint(1.0f / s0) & 0xFFFFFF00u) | (unsigned)a0;
    unsigned int u1 = (__float_as_uint(1.0f / s1) & 0xFFFFFF00u) | (unsigned)a1;
    unsigned int u2 = (__float_as_uint(1.0f / s2) & 0xFFFFFF00u) | (unsigned)a2;
    unsigned int u3 = (__float_as_uint(1.0f / s3) & 0xFFFFFF00u) | (unsigned)a3;

    *reinterpret_cast<uint4*>(g_key + p0) = make_uint4(u0, u1, u2, u3);

#define H1(U, A) {                                                             \
        int bin = (int)((U) >> 18) - (int)BASE1;                               \
        bin = bin < 0 ? 0 : (bin > BINS1 - 1 ? BINS1 - 1 : bin);               \
        atomicAdd(&shist[(unsigned)(A) * BINS1 + (unsigned)bin], 1u); }
    H1(u0, a0); H1(u1, a1); H1(u2, a2); H1(u3, a3);
#undef H1
    __syncthreads();

#pragma unroll
    for (int i = tx; i < CC * BINS1; i += 256) {
        unsigned int v = shist[i];
        if (v) atomicAdd(&g_hist1[b * (CC * BINS1) + i], v);
    }
}

// ---------------- select threshold bin + rank (160 threads, warp scan) ------
__global__ void __launch_bounds__(160) k_sel1() {
    __shared__ unsigned wsum[32];
    __shared__ unsigned tot;
    int bc = blockIdx.x;
    int t  = threadIdx.x;

    unsigned v = g_hist1[bc * BINS1 + t];
    unsigned suf = suffix_scan(v, t, 5, wsum);
    if (t == 0) tot = suf;
    __syncthreads();

    unsigned k = (unsigned)floorf((float)tot * 0.66f);
    if (k == 0) {
        if (t == 0) { g_binT[bc] = 0xFFFFFFFFu; g_r[bc] = 0; }
    } else if (v && suf >= k && suf - v < k) {
        g_binT[bc] = (unsigned)t + BASE1;
        g_r[bc]    = k - (suf - v);
    }
    g_hist1[bc * BINS1 + t] = 0;                // clean for next replay
}

// ---------------- compact + definite-pixel sum (segmented counters) ---------
__global__ void __launch_bounds__(256) k_compact() {
    __shared__ unsigned sbinT[CC];
    __shared__ float red[256];
    unsigned int tx = threadIdx.x;
    unsigned int t  = blockIdx.x * 256 + tx;
    unsigned int p0 = t << 2;
    unsigned int b  = blockIdx.x >> 9;
    unsigned int seg = blockIdx.x & (NSEG - 1);
    if (tx < CC) sbinT[tx] = g_binT[b * CC + tx];
    __syncthreads();

    uint4 u = *reinterpret_cast<const uint4*>(g_key + p0);

    float local = 0.f;
#define LANE(U) {                                                              \
        unsigned c = (U) & 255u;                                               \
        unsigned bt = sbinT[c];                                                \
        unsigned bin = (U) >> 18;                                              \
        float p = __uint_as_float((U) & 0xFFFFFF00u);                          \
        if (bin > bt) local += -__logf(p);                                     \
        else if (bin == bt) {                                                  \
            unsigned slot = (b * CC + c) * NSEG + seg;                         \
            unsigned pos = atomicAdd(&g_eqn[slot], 1u);                        \
            if (pos < SEGCAP) g_cand[slot * SEGCAP + pos] = (U);               \
        } else if (p > 0.9f) local += -__logf(p); }
    LANE(u.x); LANE(u.y); LANE(u.z); LANE(u.w);
#undef LANE

    red[tx] = local;
    __syncthreads();
#pragma unroll
    for (int s = 128; s > 0; s >>= 1) {
        if (tx < s) red[tx] += red[tx + s];
        __syncthreads();
    }
    if (tx == 0) g_blocksum[blockIdx.x] = red[0];
}

// ---------------- exact threshold among candidates + final scalar -----------
__global__ void __launch_bounds__(512) k_selfine(float* __restrict__ out) {
    __shared__ unsigned hist[512];
    __shared__ unsigned wsum[32];
    __shared__ unsigned scnt[NSEG];
    __shared__ unsigned sb1, sr2, stb, sm;
    __shared__ float red[512];
    __shared__ bool last;
    int bc = blockIdx.x;
    int t  = threadIdx.x;
    unsigned lane = t & 31, w = (unsigned)t >> 5;   // 16 warps

    unsigned binT = g_binT[bc];
    float eq = 0.f;

    if (t < NSEG) {
        unsigned c = g_eqn[bc * NSEG + t];
        scnt[t] = c > SEGCAP ? SEGCAP : c;
        g_eqn[bc * NSEG + t] = 0;                   // reset for next replay
    }
    if (t == 0) { stb = 0u; sm = 0u; }
    __syncthreads();

    if (binT != 0xFFFFFFFFu) {
        unsigned r = g_r[bc];
        const unsigned* cand = g_cand + (size_t)bc * NSEG * SEGCAP;

        // level 1: bits 17..9 of key
        hist[t] = 0; __syncthreads();
#pragma unroll
        for (int ss = 0; ss < 2; ss++) {
            unsigned seg = w + 16 * ss;
            unsigned cnt = scnt[seg];
            for (unsigned i = lane; i < cnt; i += 32)
                atomicAdd(&hist[(cand[seg * SEGCAP + i] >> 9) & 511u], 1u);
        }
        __syncthreads();
        unsigned v = hist[t];
        unsigned suf = suffix_scan(v, t, 16, wsum);
        if (v && suf >= r && suf - v < r) { sb1 = (unsigned)t; sr2 = r - (suf - v); }
        __syncthreads();
        unsigned b1 = sb1, r2 = sr2;

        // level 2: bits 8..0 of key (class byte constant within bc)
        hist[t] = 0; __syncthreads();
#pragma unroll
        for (int ss = 0; ss < 2; ss++) {
            unsigned seg = w + 16 * ss;
            unsigned cnt = scnt[seg];
            for (unsigned i = lane; i < cnt; i += 32) {
                unsigned u = cand[seg * SEGCAP + i];
                if (((u >> 9) & 511u) == b1) atomicAdd(&hist[u & 511u], 1u);
            }
        }
        __syncthreads();
        v = hist[t];
        suf = suffix_scan(v, t, 16, wsum);
        if (v && suf >= r2 && suf - v < r2) {
            stb = (binT << 18) | (b1 << 9) | (unsigned)t;
            sm  = r2 - (suf - v);
        }
        __syncthreads();
        unsigned tb = stb, m = sm;

        // candidate contributions: strictly above tb, or prob mask
#pragma unroll
        for (int ss = 0; ss < 2; ss++) {
            unsigned seg = w + 16 * ss;
            unsigned cnt = scnt[seg];
            for (unsigned i = lane; i < cnt; i += 32) {
                unsigned u = cand[seg * SEGCAP + i];
                float p = __uint_as_float(u & 0xFFFFFF00u);
                if (u > tb || p > 0.9f) eq += -__logf(p);
            }
        }
        float ptb = __uint_as_float(tb & 0xFFFFFF00u);
        if (t == 0 && ptb <= 0.9f) eq += (float)m * (-__logf(ptb));
    }

    red[t] = eq;
    __syncthreads();
#pragma unroll
    for (int s = 256; s > 0; s >>= 1) {
        if (t < s) red[t] += red[t + s];
        __syncthreads();
    }
    if (t == 0) {
        g_eqsum[bc] = red[0];
        __threadfence();
        last = (atomicAdd(&g_done, 1u) == NBC - 1);
    }
    __syncthreads();

    if (last) {
        __shared__ double dred[512];
        double acc = 0.0;
        for (int i = t; i < NBLK_MAIN; i += 512) acc += (double)g_blocksum[i];
        if (t < NBC) acc += (double)g_eqsum[t];
        dred[t] = acc;
        __syncthreads();
#pragma unroll
        for (int s = 256; s > 0; s >>= 1) {
            if (t < s) dred[t] += dred[t + s];
            __syncthreads();
        }
        if (t == 0) {
            out[0] = (float)(dred[0] * (1.0 / (double)NPIX));
            g_done = 0;
        }
    }
}

// ---------------- launcher ---------------------------------------------------
extern "C" void kernel_launch(void* const* d_in, const int* in_sizes, int n_in,
                              void* d_out, int out_size) {
    const float* pred = (const float*)d_in[0];
    float* out = (float*)d_out;
    (void)in_sizes; (void)n_in; (void)out_size;

    k_compute<<<NBLK_MAIN, 256>>>(pred);
    k_sel1<<<NBC, BINS1>>>();
    k_compact<<<NBLK_MAIN, 256>>>();
    k_selfine<<<NBC, 512>>>(out);
}